// round 1
// baseline (speedup 1.0000x reference)
#include <cuda_runtime.h>
#include <math.h>

// ---------------------------------------------------------------------------
// Problem constants
// ---------------------------------------------------------------------------
#define B_   4
#define N_   2048
#define D_   768
#define H_   12
#define HD_  64                    // head dim
#define M_   (B_ * N_)             // 8192 flattened rows
#define QKV_COLS (3 * D_)          // 2304

// Scratch (alloc-free rule: __device__ globals)
__device__ float g_qkv[(size_t)M_ * QKV_COLS];   // [B*N, 3D]  ~75.5 MB
__device__ float g_att[(size_t)M_ * D_];         // [B*N, D]   ~25 MB

// ---------------------------------------------------------------------------
// SGEMM: C[M,N] = A[M,K] @ B[K,N] (+ bias). 128x128 block tile, BK=8,
// 256 threads, 8x8 per thread. All dims multiples of tile sizes here.
// ---------------------------------------------------------------------------
template<bool BIAS>
__global__ __launch_bounds__(256) void sgemm128(
    const float* __restrict__ A, const float* __restrict__ Bm,
    const float* __restrict__ bias, float* __restrict__ C,
    int M, int N, int K)
{
    __shared__ float As[8][128];   // transposed A tile: As[k][m]
    __shared__ float Bs[8][128];   // Bs[k][n]

    const int tid = threadIdx.x;
    const int tx  = tid & 15;      // 0..15 -> 8 cols each
    const int ty  = tid >> 4;      // 0..15 -> 8 rows each
    const int row0 = blockIdx.y * 128;
    const int col0 = blockIdx.x * 128;

    const int arow = tid >> 1;           // 0..127
    const int acol = (tid & 1) * 4;      // 0 or 4
    const int brow = tid >> 5;           // 0..7
    const int bcol = (tid & 31) * 4;     // 0..124

    const float* Aptr = A + (size_t)(row0 + arow) * K + acol;
    const float* Bptr = Bm + (size_t)brow * N + col0 + bcol;

    float acc[8][8];
    #pragma unroll
    for (int i = 0; i < 8; i++)
        #pragma unroll
        for (int j = 0; j < 8; j++) acc[i][j] = 0.f;

    for (int k0 = 0; k0 < K; k0 += 8) {
        float4 av = *(const float4*)(Aptr + k0);
        As[acol + 0][arow] = av.x;
        As[acol + 1][arow] = av.y;
        As[acol + 2][arow] = av.z;
        As[acol + 3][arow] = av.w;
        *(float4*)&Bs[brow][bcol] = *(const float4*)(Bptr + (size_t)k0 * N);
        __syncthreads();

        #pragma unroll
        for (int k = 0; k < 8; k++) {
            float a[8], b[8];
            *(float4*)&a[0] = *(float4*)&As[k][ty * 8];
            *(float4*)&a[4] = *(float4*)&As[k][ty * 8 + 4];
            *(float4*)&b[0] = *(float4*)&Bs[k][tx * 8];
            *(float4*)&b[4] = *(float4*)&Bs[k][tx * 8 + 4];
            #pragma unroll
            for (int i = 0; i < 8; i++)
                #pragma unroll
                for (int j = 0; j < 8; j++)
                    acc[i][j] = fmaf(a[i], b[j], acc[i][j]);
        }
        __syncthreads();
    }

    #pragma unroll
    for (int i = 0; i < 8; i++) {
        const size_t r = (size_t)(row0 + ty * 8 + i) * N;
        #pragma unroll
        for (int j = 0; j < 8; j += 4) {
            const int c = col0 + tx * 8 + j;
            float4 v = make_float4(acc[i][j], acc[i][j+1], acc[i][j+2], acc[i][j+3]);
            if (BIAS) {
                v.x += bias[c + 0]; v.y += bias[c + 1];
                v.z += bias[c + 2]; v.w += bias[c + 3];
            }
            *(float4*)&C[r + c] = v;
        }
    }
}

// ---------------------------------------------------------------------------
// Flash attention, fp32, head_dim=64. Block = 64 query rows of one (b,h).
// 256 threads as 16x16 grid, each thread owns 4 q-rows x 4 cols.
// Shared tiles: Qs[d][r], Ks[d][c], Vs[j][d], Ps[r][c], all 64 x LD.
// ---------------------------------------------------------------------------
#define LD_ 68   // padded leading dim (floats)
#define ATTN_SMEM (4 * 64 * LD_ * (int)sizeof(float))

__global__ __launch_bounds__(256) void attn_kernel(
    const float* __restrict__ qkv, float* __restrict__ out)
{
    extern __shared__ float sm[];
    float* Qs = sm;                  // [d][r]
    float* Ks = sm + 64 * LD_;       // [d][c]
    float* Vs = sm + 2 * 64 * LD_;   // [j][d]
    float* Ps = sm + 3 * 64 * LD_;   // [r][c]

    const int tid = threadIdx.x;
    const int tx = tid & 15;         // col group (4 cols)
    const int ty = tid >> 4;         // row group (4 rows)
    const int qb = blockIdx.x;       // 0..31
    const int bh = blockIdx.y;       // 0..47
    const int b  = bh / H_;
    const int h  = bh % H_;

    const size_t base = (size_t)b * N_ * QKV_COLS;
    const int qoff = h * HD_;
    const int koff = D_ + h * HD_;
    const int voff = 2 * D_ + h * HD_;

    // ---- load Q (transposed to [d][r]), pre-scaled by 1/sqrt(64) ----
    {
        const int r0 = tid >> 4;          // 0..15
        const int d  = (tid & 15) * 4;
        #pragma unroll
        for (int rr = r0; rr < 64; rr += 16) {
            const float4 q = *(const float4*)&qkv[base + (size_t)(qb * 64 + rr) * QKV_COLS + qoff + d];
            Qs[(d + 0) * LD_ + rr] = q.x * 0.125f;
            Qs[(d + 1) * LD_ + rr] = q.y * 0.125f;
            Qs[(d + 2) * LD_ + rr] = q.z * 0.125f;
            Qs[(d + 3) * LD_ + rr] = q.w * 0.125f;
        }
    }

    float m_i[4], l_i[4], O[4][4];
    #pragma unroll
    for (int i = 0; i < 4; i++) {
        m_i[i] = -INFINITY; l_i[i] = 0.f;
        #pragma unroll
        for (int c = 0; c < 4; c++) O[i][c] = 0.f;
    }

    for (int t = 0; t < N_ / 64; t++) {
        __syncthreads();   // protect Ks/Vs from prior-iteration readers
        // ---- load K (transposed [d][c]) and V ([j][d]) ----
        {
            const int r0 = tid >> 4;
            const int d  = (tid & 15) * 4;
            #pragma unroll
            for (int rr = r0; rr < 64; rr += 16) {
                const size_t grow = base + (size_t)(t * 64 + rr) * QKV_COLS;
                const float4 kk = *(const float4*)&qkv[grow + koff + d];
                Ks[(d + 0) * LD_ + rr] = kk.x;
                Ks[(d + 1) * LD_ + rr] = kk.y;
                Ks[(d + 2) * LD_ + rr] = kk.z;
                Ks[(d + 3) * LD_ + rr] = kk.w;
                *(float4*)&Vs[rr * LD_ + d] = *(const float4*)&qkv[grow + voff + d];
            }
        }
        __syncthreads();

        // ---- S = Q @ K^T (64x64x64) ----
        float s[4][4];
        #pragma unroll
        for (int i = 0; i < 4; i++)
            #pragma unroll
            for (int j = 0; j < 4; j++) s[i][j] = 0.f;

        #pragma unroll 4
        for (int d0 = 0; d0 < 64; d0++) {
            const float4 qv = *(const float4*)&Qs[d0 * LD_ + 4 * ty];
            const float4 kk = *(const float4*)&Ks[d0 * LD_ + 4 * tx];
            const float qa[4] = {qv.x, qv.y, qv.z, qv.w};
            const float kb[4] = {kk.x, kk.y, kk.z, kk.w};
            #pragma unroll
            for (int i = 0; i < 4; i++)
                #pragma unroll
                for (int j = 0; j < 4; j++)
                    s[i][j] = fmaf(qa[i], kb[j], s[i][j]);
        }

        // ---- online softmax update ----
        #pragma unroll
        for (int i = 0; i < 4; i++) {
            float rm = fmaxf(fmaxf(s[i][0], s[i][1]), fmaxf(s[i][2], s[i][3]));
            #pragma unroll
            for (int msk = 8; msk >= 1; msk >>= 1)
                rm = fmaxf(rm, __shfl_xor_sync(0xffffffffu, rm, msk));
            const float mnew = fmaxf(m_i[i], rm);
            const float sc = __expf(m_i[i] - mnew);
            float p[4], rs = 0.f;
            #pragma unroll
            for (int j = 0; j < 4; j++) { p[j] = __expf(s[i][j] - mnew); rs += p[j]; }
            #pragma unroll
            for (int msk = 8; msk >= 1; msk >>= 1)
                rs += __shfl_xor_sync(0xffffffffu, rs, msk);
            l_i[i] = l_i[i] * sc + rs;
            m_i[i] = mnew;
            #pragma unroll
            for (int c = 0; c < 4; c++) O[i][c] *= sc;
            *(float4*)&Ps[(4 * ty + i) * LD_ + 4 * tx] = make_float4(p[0], p[1], p[2], p[3]);
        }
        __syncthreads();

        // ---- O += P @ V (64x64x64) ----
        #pragma unroll 4
        for (int j0 = 0; j0 < 64; j0++) {
            const float4 vv = *(const float4*)&Vs[j0 * LD_ + 4 * tx];
            const float vb[4] = {vv.x, vv.y, vv.z, vv.w};
            #pragma unroll
            for (int i = 0; i < 4; i++) {
                const float pr = Ps[(4 * ty + i) * LD_ + j0];
                #pragma unroll
                for (int c = 0; c < 4; c++)
                    O[i][c] = fmaf(pr, vb[c], O[i][c]);
            }
        }
    }

    // ---- finalize + write out in [B,N,D] layout ----
    #pragma unroll
    for (int i = 0; i < 4; i++) {
        const float inv = 1.f / l_i[i];
        const int n = qb * 64 + 4 * ty + i;
        float4 o = make_float4(O[i][0] * inv, O[i][1] * inv, O[i][2] * inv, O[i][3] * inv);
        *(float4*)&out[((size_t)b * N_ + n) * D_ + h * HD_ + 4 * tx] = o;
    }
}

// ---------------------------------------------------------------------------
// Launch
// ---------------------------------------------------------------------------
extern "C" void kernel_launch(void* const* d_in, const int* in_sizes, int n_in,
                              void* d_out, int out_size)
{
    const float* x      = (const float*)d_in[0];
    const float* w_qkv  = (const float*)d_in[1];
    const float* w_proj = (const float*)d_in[2];
    const float* b_proj = (const float*)d_in[3];
    float* out = (float*)d_out;

    float *qkv, *att;
    cudaGetSymbolAddress((void**)&qkv, g_qkv);
    cudaGetSymbolAddress((void**)&att, g_att);

    cudaFuncSetAttribute(attn_kernel, cudaFuncAttributeMaxDynamicSharedMemorySize, ATTN_SMEM);

    // 1) QKV = X @ W_qkv : [8192,768] x [768,2304]
    sgemm128<false><<<dim3(QKV_COLS / 128, M_ / 128), 256>>>(
        x, w_qkv, nullptr, qkv, M_, QKV_COLS, D_);

    // 2) fused flash attention -> [B,N,D]
    attn_kernel<<<dim3(N_ / 64, B_ * H_), 256, ATTN_SMEM>>>(qkv, att);

    // 3) OUT = ATT @ W_proj + b : [8192,768] x [768,768]
    sgemm128<true><<<dim3(D_ / 128, M_ / 128), 256>>>(
        att, w_proj, b_proj, out, M_, D_, D_);
}